// round 10
// baseline (speedup 1.0000x reference)
#include <cuda_runtime.h>

#define NPTS    2048
#define NPAIR   (NPTS/2)             // 1024 point-pairs
#define UPR     10
#define NJIT    (NPTS*UPR)           // 20480 jittered queries
#define QTOT    (NJIT + NPTS)        // 22528
#define KNN     5
#define T1      256
#define SPLIT   8
#define QPB     (T1/SPLIT)           // 32 queries per block
#define GX1     (QTOT/QPB)           // 704  (x2 clouds in grid.y)
#define NB2     (QTOT/256)           // 88
#define EPS_D   1e-8f
#define EPS_N   1e-10f
#define BETA    3.0f
#define STDV    0.05f
#define IDXMASK 0xFFFFF800u          // high 21 bits = d2, low 11 bits = point index

__device__ float4 g_grad[2][QTOT];   // normalized weighted gradient per (cloud,query)
__device__ float  g_partial[NB2];

__device__ __forceinline__ void ins5key(int key, int& s0, int& s1, int& s2, int& s3, int& s4) {
    s4 = key;
    int a;
    a = min(s3, s4); s4 = max(s3, s4); s3 = a;
    a = min(s2, s3); s3 = max(s2, s3); s2 = a;
    a = min(s1, s2); s2 = max(s1, s2); s1 = a;
    a = min(s0, s1); s1 = max(s0, s1); s0 = a;
}

__device__ __forceinline__ void merge_keys(int msk, int& s0, int& s1, int& s2, int& s3, int& s4) {
    int o0 = __shfl_xor_sync(0xFFFFFFFFu, s0, msk);
    int o1 = __shfl_xor_sync(0xFFFFFFFFu, s1, msk);
    int o2 = __shfl_xor_sync(0xFFFFFFFFu, s2, msk);
    int o3 = __shfl_xor_sync(0xFFFFFFFFu, s3, msk);
    int o4 = __shfl_xor_sync(0xFFFFFFFFu, s4, msk);
    if (o0 < s4) ins5key(o0, s0, s1, s2, s3, s4);
    if (o1 < s4) ins5key(o1, s0, s1, s2, s3, s4);
    if (o2 < s4) ins5key(o2, s0, s1, s2, s3, s4);
    if (o3 < s4) ins5key(o3, s0, s1, s2, s3, s4);
    if (o4 < s4) ins5key(o4, s0, s1, s2, s3, s4);
}

__device__ __forceinline__ unsigned long long packf2(float lo, float hi) {
    unsigned long long r;
    asm("mov.b64 %0, {%1, %2};" : "=l"(r) : "f"(lo), "f"(hi));
    return r;
}

__global__ __launch_bounds__(T1)
void knn_main(const float* __restrict__ src,
              const float* __restrict__ tgt,
              const float* __restrict__ noise)
{
    // Pair-SoA layout: sC[2p] = {x0,x1,y0,y1}, sC[2p+1] = {z0,z1,w0,w1}
    __shared__ float4 sC[NPTS];      // 32 KB

    const int tid   = threadIdx.x;
    const int cloud = blockIdx.y;
    const float* __restrict__ pts = cloud ? src : tgt;

    for (int i = tid; i < NPTS; i += T1) {
        float x = pts[3*i], y = pts[3*i+1], z = pts[3*i+2];
        float w = fmaf(x, x, fmaf(y, y, z * z));
        int pj = i >> 1, h = i & 1;
        float* base = (float*)&sC[2 * pj];
        base[0 + h] = x;
        base[2 + h] = y;
        base[4 + h] = z;
        base[6 + h] = w;
    }
    __syncthreads();

    const int qi  = blockIdx.x * QPB + (tid >> 3);
    const int par = tid & 7;

    // Build query point.
    float qx, qy, qz;
    if (qi < NJIT) {
        int m = qi / UPR;
        qx = fmaf(noise[3*qi + 0], STDV, tgt[3*m + 0]);
        qy = fmaf(noise[3*qi + 1], STDV, tgt[3*m + 1]);
        qz = fmaf(noise[3*qi + 2], STDV, tgt[3*m + 2]);
    } else {
        int m = qi - NJIT;
        qx = src[3*m + 0]; qy = src[3*m + 1]; qz = src[3*m + 2];
    }
    const float qx2 = -2.0f * qx, qy2 = -2.0f * qy, qz2 = -2.0f * qz;
    const float q2  = fmaf(qx, qx, fmaf(qy, qy, qz * qz));
    const unsigned long long qxp = packf2(qx2, qx2);
    const unsigned long long qyp = packf2(qy2, qy2);
    const unsigned long long qzp = packf2(qz2, qz2);

    int s0 = 0x7F000000, s1 = 0x7F000001, s2 = 0x7F000002,
        s3 = 0x7F000003, s4 = 0x7F000004;
    float thr = __int_as_float(s4) - q2;   // threshold in r-space

    // Each lane owns pairs pj = 8*k + par  (256 points / lane).
#pragma unroll 8
    for (int k = 0; k < NPAIR / SPLIT; ++k) {
        int pj = (k << 3) + par;
        float4 a = sC[2 * pj];       // {x0,x1,y0,y1}
        float4 b = sC[2 * pj + 1];   // {z0,z1,w0,w1}
        unsigned long long xx = packf2(a.x, a.y);
        unsigned long long yy = packf2(a.z, a.w);
        unsigned long long zz = packf2(b.x, b.y);
        unsigned long long ww = packf2(b.z, b.w);
        unsigned long long r01;
        asm("fma.rn.f32x2 %0, %1, %2, %3;" : "=l"(r01) : "l"(zz), "l"(qzp), "l"(ww));
        asm("fma.rn.f32x2 %0, %1, %2, %3;" : "=l"(r01) : "l"(yy), "l"(qyp), "l"(r01));
        asm("fma.rn.f32x2 %0, %1, %2, %3;" : "=l"(r01) : "l"(xx), "l"(qxp), "l"(r01));
        float r0, r1;
        asm("mov.b64 {%0, %1}, %2;" : "=f"(r0), "=f"(r1) : "l"(r01));

        if (fminf(r0, r1) < thr) {
            if (r0 < thr) {
                float d2 = r0 + q2;
                int key = (int)((__float_as_uint(d2) & IDXMASK) | (unsigned)(2 * pj));
                ins5key(key, s0, s1, s2, s3, s4);
                thr = __int_as_float(s4) - q2;
            }
            if (r1 < thr) {
                float d2 = r1 + q2;
                int key = (int)((__float_as_uint(d2) & IDXMASK) | (unsigned)(2 * pj + 1));
                ins5key(key, s0, s1, s2, s3, s4);
                thr = __int_as_float(s4) - q2;
            }
        }
    }

    merge_keys(1, s0, s1, s2, s3, s4);
    merge_keys(2, s0, s1, s2, s3, s4);
    merge_keys(4, s0, s1, s2, s3, s4);

    if (par == 0) {
        float aw = 0.f, gx = 0.f, gy = 0.f, gz = 0.f;
        int keys[KNN] = {s0, s1, s2, s3, s4};
#pragma unroll
        for (int kk = 0; kk < KNN; ++kk) {
            int idx = keys[kk] & 2047;
            int pj = idx >> 1, h = idx & 1;
            const float* base = (const float*)&sC[2 * pj];
            float x = base[0 + h], y = base[2 + h], z = base[4 + h];
            float dx = qx - x, dy = qy - y, dz = qz - z;
            float d2 = fmaf(dx, dx, fmaf(dy, dy, dz * dz));   // exact, non-negative
            float w  = 1.0f / (d2 + EPS_D);
            aw += w;
            gx = fmaf(dx, w, gx);
            gy = fmaf(dy, w, gy);
            gz = fmaf(dz, w, gz);
        }
        float inv = 1.0f / aw;
        g_grad[cloud][qi] = make_float4(gx * inv, gy * inv, gz * inv, 0.f);
    }
}

__global__ __launch_bounds__(256)
void combine_kernel()
{
    __shared__ float sh[8];
    const int tid = threadIdx.x;
    const int qi  = blockIdx.x * 256 + tid;

    float4 gT = g_grad[0][qi];
    float4 gS = g_grad[1][qi];

    float axT = gT.x + EPS_N, ayT = gT.y + EPS_N, azT = gT.z + EPS_N;
    float axS = gS.x + EPS_N, ayS = gS.y + EPS_N, azS = gS.z + EPS_N;
    float uT = sqrtf(fmaf(axT, axT, fmaf(ayT, ayT, azT * azT)));
    float uS = sqrtf(fmaf(axS, axS, fmaf(ayS, ayS, azS * azS)));

    float e1 = fabsf(uT - uS);
    float e2 = fabsf(gS.x - gT.x) + fabsf(gS.y - gT.y) + fabsf(gS.z - gT.z);
    float t  = e1 + e2;
    float v  = t * __expf(-BETA * t);

#pragma unroll
    for (int o = 16; o > 0; o >>= 1) v += __shfl_down_sync(0xFFFFFFFFu, v, o);
    if ((tid & 31) == 0) sh[tid >> 5] = v;
    __syncthreads();
    if (tid == 0) {
        float s = 0.f;
#pragma unroll
        for (int w = 0; w < 8; ++w) s += sh[w];
        g_partial[blockIdx.x] = s;
    }
}

__global__ void final_reduce(float* __restrict__ out)
{
    __shared__ float sh[4];
    int tid = threadIdx.x;   // 128
    float v = (tid < NB2) ? g_partial[tid] : 0.f;
#pragma unroll
    for (int o = 16; o > 0; o >>= 1) v += __shfl_down_sync(0xFFFFFFFFu, v, o);
    if ((tid & 31) == 0) sh[tid >> 5] = v;
    __syncthreads();
    if (tid == 0) {
        float s = sh[0] + sh[1] + sh[2] + sh[3];
        out[0] = s * (1.0f / (float)QTOT);
    }
}

extern "C" void kernel_launch(void* const* d_in, const int* in_sizes, int n_in,
                              void* d_out, int out_size)
{
    const float* src   = (const float*)d_in[0];
    const float* tgt   = (const float*)d_in[1];
    const float* noise = (const float*)d_in[2];
    (void)in_sizes; (void)n_in; (void)out_size;

    knn_main<<<dim3(GX1, 2), T1>>>(src, tgt, noise);
    combine_kernel<<<NB2, 256>>>();
    final_reduce<<<1, 128>>>((float*)d_out);
}

// round 11
// speedup vs baseline: 1.5896x; 1.5896x over previous
#include <cuda_runtime.h>

#define NPTS    2048
#define NPAIR   (NPTS/2)             // 1024 point-pairs
#define UPR     10
#define NJIT    (NPTS*UPR)           // 20480 jittered queries
#define QTOT    (NJIT + NPTS)        // 22528
#define KNN     5
#define T1      256
#define SPLIT   4
#define QPB     (T1/SPLIT)           // 64 queries per block
#define GX1     (QTOT/QPB)           // 352  (x2 clouds in grid.y)
#define NB2     (QTOT/256)           // 88
#define EPS_D   1e-8f
#define EPS_N   1e-10f
#define BETA    3.0f
#define STDV    0.05f
#define IDXMASK 0xFFFFF800u          // high 21 bits = d2, low 11 bits = point index

__device__ float4 g_grad[2][QTOT];   // normalized weighted gradient per (cloud,query)
__device__ float  g_partial[NB2];

__device__ __forceinline__ void ins5key(int key, int& s0, int& s1, int& s2, int& s3, int& s4) {
    s4 = key;
    int a;
    a = min(s3, s4); s4 = max(s3, s4); s3 = a;
    a = min(s2, s3); s3 = max(s2, s3); s2 = a;
    a = min(s1, s2); s2 = max(s1, s2); s1 = a;
    a = min(s0, s1); s1 = max(s0, s1); s0 = a;
}

__device__ __forceinline__ void merge_keys(int msk, int& s0, int& s1, int& s2, int& s3, int& s4) {
    int o0 = __shfl_xor_sync(0xFFFFFFFFu, s0, msk);
    int o1 = __shfl_xor_sync(0xFFFFFFFFu, s1, msk);
    int o2 = __shfl_xor_sync(0xFFFFFFFFu, s2, msk);
    int o3 = __shfl_xor_sync(0xFFFFFFFFu, s3, msk);
    int o4 = __shfl_xor_sync(0xFFFFFFFFu, s4, msk);
    if (o0 < s4) ins5key(o0, s0, s1, s2, s3, s4);
    if (o1 < s4) ins5key(o1, s0, s1, s2, s3, s4);
    if (o2 < s4) ins5key(o2, s0, s1, s2, s3, s4);
    if (o3 < s4) ins5key(o3, s0, s1, s2, s3, s4);
    if (o4 < s4) ins5key(o4, s0, s1, s2, s3, s4);
}

__device__ __forceinline__ unsigned long long packf2(float lo, float hi) {
    unsigned long long r;
    asm("mov.b64 %0, {%1, %2};" : "=l"(r) : "f"(lo), "f"(hi));
    return r;
}

__global__ __launch_bounds__(T1)
void knn_main(const float* __restrict__ src,
              const float* __restrict__ tgt,
              const float* __restrict__ noise)
{
    // Pair-SoA layout: sC[2p] = {x0,x1,y0,y1}, sC[2p+1] = {z0,z1,w0,w1}
    // Loaded as ulonglong2: .x/.y are already f32x2-packed coordinate pairs.
    __shared__ float4 sC[NPTS];      // 32 KB

    const int tid   = threadIdx.x;
    const int cloud = blockIdx.y;
    const float* __restrict__ pts = cloud ? src : tgt;

    for (int i = tid; i < NPTS; i += T1) {
        float x = pts[3*i], y = pts[3*i+1], z = pts[3*i+2];
        float w = fmaf(x, x, fmaf(y, y, z * z));
        int pj = i >> 1, h = i & 1;
        float* base = (float*)&sC[2 * pj];
        base[0 + h] = x;
        base[2 + h] = y;
        base[4 + h] = z;
        base[6 + h] = w;
    }
    __syncthreads();

    const int qi  = blockIdx.x * QPB + (tid >> 2);
    const int par = tid & 3;

    // Build query point.
    float qx, qy, qz;
    if (qi < NJIT) {
        int m = qi / UPR;
        qx = fmaf(noise[3*qi + 0], STDV, tgt[3*m + 0]);
        qy = fmaf(noise[3*qi + 1], STDV, tgt[3*m + 1]);
        qz = fmaf(noise[3*qi + 2], STDV, tgt[3*m + 2]);
    } else {
        int m = qi - NJIT;
        qx = src[3*m + 0]; qy = src[3*m + 1]; qz = src[3*m + 2];
    }
    const float qx2 = -2.0f * qx, qy2 = -2.0f * qy, qz2 = -2.0f * qz;
    const float q2  = fmaf(qx, qx, fmaf(qy, qy, qz * qz));
    const unsigned long long qxp = packf2(qx2, qx2);   // hoisted, once
    const unsigned long long qyp = packf2(qy2, qy2);
    const unsigned long long qzp = packf2(qz2, qz2);

    int s0 = 0x7F000000, s1 = 0x7F000001, s2 = 0x7F000002,
        s3 = 0x7F000003, s4 = 0x7F000004;
    float thr = __int_as_float(s4) - q2;   // threshold in r-space

    // Each lane owns pairs pj = 4*k + par. Walk smem as ulonglong2 (16B elems):
    // pair pj occupies elements {2pj, 2pj+1}; stride per k = 8 elements.
    const ulonglong2* pc = reinterpret_cast<const ulonglong2*>(sC) + 2 * par;

#pragma unroll 8
    for (int k = 0; k < NPAIR / SPLIT; ++k) {
        ulonglong2 A = pc[8 * k];        // {x-pair, y-pair}
        ulonglong2 B = pc[8 * k + 1];    // {z-pair, w-pair}
        unsigned long long r01;
        asm("fma.rn.f32x2 %0, %1, %2, %3;" : "=l"(r01) : "l"(B.x), "l"(qzp), "l"(B.y));
        asm("fma.rn.f32x2 %0, %1, %2, %3;" : "=l"(r01) : "l"(A.y), "l"(qyp), "l"(r01));
        asm("fma.rn.f32x2 %0, %1, %2, %3;" : "=l"(r01) : "l"(A.x), "l"(qxp), "l"(r01));
        float r0, r1;
        asm("mov.b64 {%0, %1}, %2;" : "=f"(r0), "=f"(r1) : "l"(r01));

        if (fminf(r0, r1) < thr) {
            int jbase = (k << 3) + 2 * par;   // = 2*pj : point index of r0
            if (r0 < thr) {
                float d2 = r0 + q2;
                int key = (int)((__float_as_uint(d2) & IDXMASK) | (unsigned)jbase);
                ins5key(key, s0, s1, s2, s3, s4);
                thr = __int_as_float(s4) - q2;
            }
            if (r1 < thr) {
                float d2 = r1 + q2;
                int key = (int)((__float_as_uint(d2) & IDXMASK) | (unsigned)(jbase + 1));
                ins5key(key, s0, s1, s2, s3, s4);
                thr = __int_as_float(s4) - q2;
            }
        }
    }

    merge_keys(1, s0, s1, s2, s3, s4);
    merge_keys(2, s0, s1, s2, s3, s4);

    if (par == 0) {
        float aw = 0.f, gx = 0.f, gy = 0.f, gz = 0.f;
        int keys[KNN] = {s0, s1, s2, s3, s4};
#pragma unroll
        for (int kk = 0; kk < KNN; ++kk) {
            int idx = keys[kk] & 2047;
            int pj = idx >> 1, h = idx & 1;
            const float* base = (const float*)&sC[2 * pj];
            float x = base[0 + h], y = base[2 + h], z = base[4 + h];
            float dx = qx - x, dy = qy - y, dz = qz - z;
            float d2 = fmaf(dx, dx, fmaf(dy, dy, dz * dz));   // exact, non-negative
            float w  = 1.0f / (d2 + EPS_D);
            aw += w;
            gx = fmaf(dx, w, gx);
            gy = fmaf(dy, w, gy);
            gz = fmaf(dz, w, gz);
        }
        float inv = 1.0f / aw;
        g_grad[cloud][qi] = make_float4(gx * inv, gy * inv, gz * inv, 0.f);
    }
}

__global__ __launch_bounds__(256)
void combine_kernel()
{
    __shared__ float sh[8];
    const int tid = threadIdx.x;
    const int qi  = blockIdx.x * 256 + tid;

    float4 gT = g_grad[0][qi];
    float4 gS = g_grad[1][qi];

    float axT = gT.x + EPS_N, ayT = gT.y + EPS_N, azT = gT.z + EPS_N;
    float axS = gS.x + EPS_N, ayS = gS.y + EPS_N, azS = gS.z + EPS_N;
    float uT = sqrtf(fmaf(axT, axT, fmaf(ayT, ayT, azT * azT)));
    float uS = sqrtf(fmaf(axS, axS, fmaf(ayS, ayS, azS * azS)));

    float e1 = fabsf(uT - uS);
    float e2 = fabsf(gS.x - gT.x) + fabsf(gS.y - gT.y) + fabsf(gS.z - gT.z);
    float t  = e1 + e2;
    float v  = t * __expf(-BETA * t);

#pragma unroll
    for (int o = 16; o > 0; o >>= 1) v += __shfl_down_sync(0xFFFFFFFFu, v, o);
    if ((tid & 31) == 0) sh[tid >> 5] = v;
    __syncthreads();
    if (tid == 0) {
        float s = 0.f;
#pragma unroll
        for (int w = 0; w < 8; ++w) s += sh[w];
        g_partial[blockIdx.x] = s;
    }
}

__global__ void final_reduce(float* __restrict__ out)
{
    __shared__ float sh[4];
    int tid = threadIdx.x;   // 128
    float v = (tid < NB2) ? g_partial[tid] : 0.f;
#pragma unroll
    for (int o = 16; o > 0; o >>= 1) v += __shfl_down_sync(0xFFFFFFFFu, v, o);
    if ((tid & 31) == 0) sh[tid >> 5] = v;
    __syncthreads();
    if (tid == 0) {
        float s = sh[0] + sh[1] + sh[2] + sh[3];
        out[0] = s * (1.0f / (float)QTOT);
    }
}

extern "C" void kernel_launch(void* const* d_in, const int* in_sizes, int n_in,
                              void* d_out, int out_size)
{
    const float* src   = (const float*)d_in[0];
    const float* tgt   = (const float*)d_in[1];
    const float* noise = (const float*)d_in[2];
    (void)in_sizes; (void)n_in; (void)out_size;

    knn_main<<<dim3(GX1, 2), T1>>>(src, tgt, noise);
    combine_kernel<<<NB2, 256>>>();
    final_reduce<<<1, 128>>>((float*)d_out);
}